// round 6
// baseline (speedup 1.0000x reference)
#include <cuda_runtime.h>
#include <stdint.h>

// Problem constants
#define B 8
#define H 12
#define L 1024
#define D 768
#define KSEL 512
#define HL (H * L)                       // 12288 rows per batch
#define SPLITS 96
#define ROWS_PER_SPLIT (HL / SPLITS)     // 128
#define L4 (L / 4)                       // 256 float4 per row
#define D4 (D / 4)                       // 192 float4 per token row

// Scratch (device globals: allocation is forbidden in kernel_launch).
// All zero at module load and reset to zero by the kernel itself at the end
// of every call -> graph-replay safe.
__device__ float g_imp[B * L];
__device__ int   g_selidx[B * KSEL];
__device__ int   g_count[B];
__device__ int   g_flag[B];
__device__ int   g_done[B];

// ---------------------------------------------------------------------------
// Single fused kernel: column sums (96-way split, float4 streaming, f32
// atomics into g_imp) -> per-batch last-arriving block runs radix top-K
// select + compact + mask write -> release flag -> ALL 96 blocks of the
// batch gather their token rows (overlapping other batches' colsum/select).
// grid (B, SPLITS), block 256, single co-resident wave (768 blocks <= 1184).
// ---------------------------------------------------------------------------
__global__ void __launch_bounds__(256) router_fused_kernel(
    const float4* __restrict__ scores4, const float* __restrict__ amask,
    const float* __restrict__ hidden,
    float* __restrict__ imp, int* __restrict__ selidx,
    int* __restrict__ count, int* __restrict__ flag, int* __restrict__ done,
    float* __restrict__ out)
{
    const int b = blockIdx.x;
    const int s = blockIdx.y;
    const int t = threadIdx.x;
    const int lane = t & 31;
    const int wid  = t >> 5;

    // ---- colsum phase: stream 128 rows, accumulate 1 float4 per thread ----
    {
        const float4* base =
            scores4 + ((size_t)b * HL + (size_t)s * ROWS_PER_SPLIT) * L4 + t;
        float4 acc = make_float4(0.f, 0.f, 0.f, 0.f);
#pragma unroll 16
        for (int r = 0; r < ROWS_PER_SPLIT; ++r) {
            const float4 x = __ldcs(base + (size_t)r * L4);
            acc.x += x.x; acc.y += x.y; acc.z += x.z; acc.w += x.w;
        }
        float* dst = imp + b * L + 4 * t;
        atomicAdd(dst + 0, acc.x);
        atomicAdd(dst + 1, acc.y);
        atomicAdd(dst + 2, acc.z);
        atomicAdd(dst + 3, acc.w);
    }

    // ---- arrival: last block per batch runs the selection ----
    __threadfence();
    __syncthreads();
    __shared__ int s_ticket;
    if (t == 0) s_ticket = atomicAdd(&count[b], 1);
    __syncthreads();

    if (s_ticket == SPLITS - 1) {
        __threadfence();               // acquire: all batch-b atomics visible

        // ---- read importance: thread t owns columns 4t..4t+3 ----
        const float4 iv = *((const float4*)(imp + b * L) + t);

        // monotonic keys
        unsigned k[4];
        {
            const float f[4] = {iv.x, iv.y, iv.z, iv.w};
#pragma unroll
            for (int i = 0; i < 4; ++i) {
                const unsigned ub = __float_as_uint(f[i]);
                k[i] = ub ^ ((ub & 0x80000000u) ? 0xFFFFFFFFu : 0x80000000u);
            }
        }

        __shared__ int      hist[256];
        __shared__ unsigned s_pref;
        __shared__ int      s_k;
        __shared__ int      wtot[8];

        if (t == 0) { s_pref = 0u; s_k = KSEL; }
        __syncthreads();

        // ---- 4-pass byte radix select: 512th-largest key + tie quota ----
#pragma unroll
        for (int pass = 0; pass < 4; ++pass) {
            const int shift = 24 - 8 * pass;
            const unsigned pref = s_pref;
            const int kcur = s_k;

            hist[t] = 0;
            __syncthreads();
#pragma unroll
            for (int i = 0; i < 4; ++i) {
                const bool active = (pass == 0) ||
                    (((k[i] ^ pref) >> (shift + 8)) == 0u);
                if (active) atomicAdd(&hist[(k[i] >> shift) & 0xFF], 1);
            }
            __syncthreads();

            // inclusive suffix sum over 256 bins via warp shfl
            const int h = hist[t];
            int v = h;
#pragma unroll
            for (int d = 1; d < 32; d <<= 1) {
                const int n = __shfl_down_sync(0xffffffffu, v, d);
                if (lane + d < 32) v += n;
            }
            const int wsum = __shfl_sync(0xffffffffu, v, 0);
            if (lane == 0) wtot[wid] = wsum;
            __syncthreads();
            int above = 0;
#pragma unroll
            for (int w = 0; w < 8; ++w) if (w > wid) above += wtot[w];
            const int ge = v + above;        // active keys with bin >= t
            const int gt = ge - h;
            if (gt < kcur && ge >= kcur) {   // exactly one bin fires
                s_pref = pref | ((unsigned)t << shift);
                s_k    = kcur - gt;
            }
            __syncthreads();
        }

        const unsigned T  = s_pref;   // threshold key (512th-largest)
        const int      kq = s_k;      // tie slots (>= 1), lowest indices win

        // ---- tie ranking (ascending index) via block scan ----
        bool tie[4];
        int tiecnt = 0;
#pragma unroll
        for (int i = 0; i < 4; ++i) { tie[i] = (k[i] == T); tiecnt += tie[i]; }

        int incl = tiecnt;
#pragma unroll
        for (int d = 1; d < 32; d <<= 1) {
            const int n = __shfl_up_sync(0xffffffffu, incl, d);
            if (lane >= d) incl += n;
        }
        if (lane == 31) wtot[wid] = incl;
        __syncthreads();
        int base = 0;
#pragma unroll
        for (int w = 0; w < 8; ++w) if (w < wid) base += wtot[w];
        int trank = base + incl - tiecnt;    // exclusive prefix of ties

        bool sel[4];
        int selcnt = 0;
#pragma unroll
        for (int i = 0; i < 4; ++i) {
            bool sl = (k[i] > T);
            if (tie[i]) { sl = (trank < kq); ++trank; }
            sel[i] = sl; selcnt += sl;
        }
        __syncthreads();                     // wtot reuse

        // ---- compaction scan (ascending index) ----
        int sincl = selcnt;
#pragma unroll
        for (int d = 1; d < 32; d <<= 1) {
            const int n = __shfl_up_sync(0xffffffffu, sincl, d);
            if (lane >= d) sincl += n;
        }
        if (lane == 31) wtot[wid] = sincl;
        __syncthreads();
        int sbase = 0;
#pragma unroll
        for (int w = 0; w < 8; ++w) if (w < wid) sbase += wtot[w];
        int pos = sbase + sincl - selcnt;    // exclusive prefix

#pragma unroll
        for (int i = 0; i < 4; ++i) {
            if (sel[i]) { selidx[b * KSEL + pos] = 4 * t + i; ++pos; }
        }

        __syncthreads();   // selidx writes visible block-wide

        // ---- final attention mask for this batch (513 floats) ----
        float* mout = out + (size_t)B * (KSEL + 1) * D
                          + (size_t)b * (KSEL + 1);
        for (int r = t; r <= KSEL; r += 256) {
            if (r == 0) mout[0] = 0.f;
            else        mout[r] = amask[(size_t)b * L
                                        + selidx[b * KSEL + r - 1]];
        }

        // ---- reset colsum scratch for the next replay ----
        *((float4*)(imp + b * L) + t) = make_float4(0.f, 0.f, 0.f, 0.f);
        if (t == 0) count[b] = 0;

        // ---- release: selidx ready for this batch ----
        __threadfence();
        __syncthreads();
        if (t == 0) atomicExch(&flag[b], 1);
    }

    // ---- all blocks: wait for this batch's selidx ----
    if (t == 0) {
        unsigned ns = 8;
        while (((volatile int*)flag)[b] == 0) {
            __nanosleep(ns);
            if (ns < 256) ns <<= 1;
        }
    }
    __syncthreads();
    __threadfence();   // acquire

    // ---- gather phase: block s copies rows r = s, s+96, ... (<= 512) ----
    if (t < D4) {
        for (int r = s; r <= KSEL; r += SPLITS) {
            const int j = (r == 0) ? 0 : selidx[b * KSEL + r - 1];
            const float4* src = (const float4*)(hidden
                                + ((size_t)b * L + j) * D) + t;
            float4* dst = (float4*)(out
                                + ((size_t)b * (KSEL + 1) + r) * D) + t;
            *dst = *src;
        }
    }

    // ---- completion: last gatherer resets the flags for next replay ----
    __syncthreads();
    if (t == 0) {
        const int d = atomicAdd(&done[b], 1);
        if (d == SPLITS - 1) {
            done[b] = 0;
            flag[b] = 0;
        }
    }
}

// ---------------------------------------------------------------------------
extern "C" void kernel_launch(void* const* d_in, const int* in_sizes, int n_in,
                              void* d_out, int out_size)
{
    const float* hidden = (const float*)d_in[0];   // [B, L, D]
    const float* amask  = (const float*)d_in[1];   // [B, 1, 1, L]
    const float* scores = (const float*)d_in[2];   // [B, H, L, L]
    float* out = (float*)d_out;                    // tokens then mask, f32

    float* d_imp;
    int *d_selidx, *d_count, *d_flag, *d_done;
    cudaGetSymbolAddress((void**)&d_imp,    g_imp);
    cudaGetSymbolAddress((void**)&d_selidx, g_selidx);
    cudaGetSymbolAddress((void**)&d_count,  g_count);
    cudaGetSymbolAddress((void**)&d_flag,   g_flag);
    cudaGetSymbolAddress((void**)&d_done,   g_done);

    dim3 grid(B, SPLITS);
    router_fused_kernel<<<grid, 256>>>(
        (const float4*)scores, amask, hidden,
        d_imp, d_selidx, d_count, d_flag, d_done, out);
}

// round 7
// speedup vs baseline: 1.0004x; 1.0004x over previous
#include <cuda_runtime.h>
#include <stdint.h>

// Problem constants
#define B 8
#define H 12
#define L 1024
#define D 768
#define KSEL 512
#define HL (H * L)                 // 12288 rows per batch
#define GROWS (B * HL)             // 98304 rows total
#define L4 (L / 4)                 // 256 float4 per row
#define D4 (D / 4)                 // 192 float4 per token row
#define NBLK 740                   // 148 SMs x 5 blocks: one perfectly even wave

// Scratch (device globals). Zero at load; kernel restores zeros each call.
__device__ float g_imp[B * L];
__device__ int   g_selidx[B * KSEL];
__device__ int   g_count[B];

// ---------------------------------------------------------------------------
// Kernel 1: balanced column sums + fused per-batch radix top-K select.
// grid NBLK, block 256. Block i owns global rows [i*GROWS/NBLK, (i+1)*GROWS/NBLK),
// split at batch boundaries (<=2 segments). Thread t owns float4 column t.
// After flushing a segment, the block that completes a batch's 12288-row count
// runs the select + compact + mask write for that batch.
// ---------------------------------------------------------------------------
__global__ void __launch_bounds__(256) colsum_select_kernel(
    const float4* __restrict__ scores4, const float* __restrict__ amask,
    float* __restrict__ imp, int* __restrict__ selidx,
    int* __restrict__ count, float* __restrict__ out)
{
    const int t = threadIdx.x;
    const int lane = t & 31;
    const int wid  = t >> 5;

    const int g0 = (int)(((long long)blockIdx.x * GROWS) / NBLK);
    const int g1 = (int)(((long long)(blockIdx.x + 1) * GROWS) / NBLK);

    __shared__ int s_trigger;

    int g = g0;
    while (g < g1) {
        const int b = g / HL;
        const int seg_end = min(g1, (b + 1) * HL);
        const int seg_rows = seg_end - g;

        // ---- accumulate this segment (float4 streaming, unroll 16) ----
        float4 acc = make_float4(0.f, 0.f, 0.f, 0.f);
        {
            const float4* p = scores4 + (size_t)g * L4 + t;
            int r = 0;
            const int full = seg_rows & ~15;
            for (; r < full; r += 16) {
#pragma unroll
                for (int u = 0; u < 16; ++u) {
                    const float4 x = __ldcs(p + (size_t)(r + u) * L4);
                    acc.x += x.x; acc.y += x.y; acc.z += x.z; acc.w += x.w;
                }
            }
            for (; r < seg_rows; ++r) {
                const float4 x = __ldcs(p + (size_t)r * L4);
                acc.x += x.x; acc.y += x.y; acc.z += x.z; acc.w += x.w;
            }
        }
        float* dst = imp + b * L + 4 * t;
        atomicAdd(dst + 0, acc.x);
        atomicAdd(dst + 1, acc.y);
        atomicAdd(dst + 2, acc.z);
        atomicAdd(dst + 3, acc.w);

        // ---- release + arrival count ----
        __threadfence();
        __syncthreads();
        if (t == 0) {
            const int old = atomicAdd(&count[b], seg_rows);
            s_trigger = (old + seg_rows == HL);
        }
        __syncthreads();

        if (s_trigger) {
            __threadfence();   // acquire: all batch-b atomics visible

            // ---- read importance: thread t owns columns 4t..4t+3 ----
            const float4 iv = *((const float4*)(imp + b * L) + t);

            unsigned k[4];
            {
                const float f[4] = {iv.x, iv.y, iv.z, iv.w};
#pragma unroll
                for (int i = 0; i < 4; ++i) {
                    const unsigned ub = __float_as_uint(f[i]);
                    k[i] = ub ^ ((ub & 0x80000000u) ? 0xFFFFFFFFu
                                                    : 0x80000000u);
                }
            }

            __shared__ int      hist[256];
            __shared__ unsigned s_pref;
            __shared__ int      s_k;
            __shared__ int      wtot[8];

            if (t == 0) { s_pref = 0u; s_k = KSEL; }
            __syncthreads();

            // ---- 4-pass byte radix select ----
#pragma unroll
            for (int pass = 0; pass < 4; ++pass) {
                const int shift = 24 - 8 * pass;
                const unsigned pref = s_pref;
                const int kcur = s_k;

                hist[t] = 0;
                __syncthreads();
#pragma unroll
                for (int i = 0; i < 4; ++i) {
                    const bool active = (pass == 0) ||
                        (((k[i] ^ pref) >> (shift + 8)) == 0u);
                    if (active) atomicAdd(&hist[(k[i] >> shift) & 0xFF], 1);
                }
                __syncthreads();

                const int h = hist[t];
                int v = h;
#pragma unroll
                for (int d = 1; d < 32; d <<= 1) {
                    const int n = __shfl_down_sync(0xffffffffu, v, d);
                    if (lane + d < 32) v += n;
                }
                const int wsum = __shfl_sync(0xffffffffu, v, 0);
                if (lane == 0) wtot[wid] = wsum;
                __syncthreads();
                int above = 0;
#pragma unroll
                for (int w = 0; w < 8; ++w) if (w > wid) above += wtot[w];
                const int ge = v + above;
                const int gt = ge - h;
                if (gt < kcur && ge >= kcur) {   // exactly one bin fires
                    s_pref = pref | ((unsigned)t << shift);
                    s_k    = kcur - gt;
                }
                __syncthreads();
            }

            const unsigned T  = s_pref;
            const int      kq = s_k;     // tie slots, lowest indices win

            // ---- tie ranking (ascending index) ----
            bool tie[4];
            int tiecnt = 0;
#pragma unroll
            for (int i = 0; i < 4; ++i) {
                tie[i] = (k[i] == T); tiecnt += tie[i];
            }
            int incl = tiecnt;
#pragma unroll
            for (int d = 1; d < 32; d <<= 1) {
                const int n = __shfl_up_sync(0xffffffffu, incl, d);
                if (lane >= d) incl += n;
            }
            if (lane == 31) wtot[wid] = incl;
            __syncthreads();
            int base = 0;
#pragma unroll
            for (int w = 0; w < 8; ++w) if (w < wid) base += wtot[w];
            int trank = base + incl - tiecnt;

            bool sel[4];
            int selcnt = 0;
#pragma unroll
            for (int i = 0; i < 4; ++i) {
                bool sl = (k[i] > T);
                if (tie[i]) { sl = (trank < kq); ++trank; }
                sel[i] = sl; selcnt += sl;
            }
            __syncthreads();

            // ---- compaction scan (ascending index) ----
            int sincl = selcnt;
#pragma unroll
            for (int d = 1; d < 32; d <<= 1) {
                const int n = __shfl_up_sync(0xffffffffu, sincl, d);
                if (lane >= d) sincl += n;
            }
            if (lane == 31) wtot[wid] = sincl;
            __syncthreads();
            int sbase = 0;
#pragma unroll
            for (int w = 0; w < 8; ++w) if (w < wid) sbase += wtot[w];
            int pos = sbase + sincl - selcnt;

#pragma unroll
            for (int i = 0; i < 4; ++i) {
                if (sel[i]) { selidx[b * KSEL + pos] = 4 * t + i; ++pos; }
            }
            __syncthreads();

            // ---- final attention mask (513 floats) ----
            float* mout = out + (size_t)B * (KSEL + 1) * D
                              + (size_t)b * (KSEL + 1);
            for (int r = t; r <= KSEL; r += 256) {
                if (r == 0) mout[0] = 0.f;
                else        mout[r] = amask[(size_t)b * L
                                            + selidx[b * KSEL + r - 1]];
            }

            // ---- reset scratch for next replay ----
            *((float4*)(imp + b * L) + t) =
                make_float4(0.f, 0.f, 0.f, 0.f);
            if (t == 0) count[b] = 0;
            __syncthreads();
        }

        g = seg_end;
    }
}

// ---------------------------------------------------------------------------
// Kernel 2: gather token rows. Row 0 = class token (j=0).
// grid (65, B), block 256: 8 rows/block, 32 lanes/row, 6 float4 per thread.
// ---------------------------------------------------------------------------
__global__ void __launch_bounds__(256) gather_kernel(
    const float* __restrict__ hs, const int* __restrict__ selidx,
    float* __restrict__ out)
{
    const int rr   = threadIdx.x >> 5;       // 0..7 row slot
    const int lane = threadIdx.x & 31;       // 0..31
    const int r = blockIdx.x * 8 + rr;       // 0..519
    const int b = blockIdx.y;
    if (r > KSEL) return;

    const int j = (r == 0) ? 0 : selidx[b * KSEL + r - 1];

    const float4* src = (const float4*)(hs + ((size_t)b * L + j) * D) + lane;
    float4* dst = (float4*)(out + ((size_t)b * (KSEL + 1) + r) * D) + lane;

    float4 v[6];
#pragma unroll
    for (int q = 0; q < 6; ++q) v[q] = src[32 * q];
#pragma unroll
    for (int q = 0; q < 6; ++q) dst[32 * q] = v[q];
}

// ---------------------------------------------------------------------------
extern "C" void kernel_launch(void* const* d_in, const int* in_sizes, int n_in,
                              void* d_out, int out_size)
{
    const float* hidden = (const float*)d_in[0];   // [B, L, D]
    const float* amask  = (const float*)d_in[1];   // [B, 1, 1, L]
    const float* scores = (const float*)d_in[2];   // [B, H, L, L]
    float* out = (float*)d_out;                    // tokens then mask, f32

    float* d_imp;
    int *d_selidx, *d_count;
    cudaGetSymbolAddress((void**)&d_imp,    g_imp);
    cudaGetSymbolAddress((void**)&d_selidx, g_selidx);
    cudaGetSymbolAddress((void**)&d_count,  g_count);

    colsum_select_kernel<<<NBLK, 256>>>(
        (const float4*)scores, amask, d_imp, d_selidx, d_count, out);

    dim3 gridC(65, B);
    gather_kernel<<<gridC, 256>>>(hidden, d_selidx, out);
}